// round 1
// baseline (speedup 1.0000x reference)
#include <cuda_runtime.h>
#include <math.h>

#define HH 256
#define WW 512
#define CC 16
#define ND 32
#define HW (HH * WW)
#define BASELINE_V 0.24f

// Output layout: out[ch, d, h, w], ch in [0,32): ch<16 -> x broadcast, ch>=16 -> warped y.
// One thread handles one (d, h, w0..w0+3) strip across all 32 channels.
__global__ __launch_bounds__(256) void cost_volume_kernel(
    const float* __restrict__ x,
    const float* __restrict__ y,
    const float* __restrict__ depth,
    float* __restrict__ out)
{
    int idx = blockIdx.x * 256 + threadIdx.x;   // ND*HH*(WW/4) = 1,048,576 threads
    int w4 = idx & 127;            // WW/4 = 128
    int h  = (idx >> 7) & 255;     // HH = 256
    int d  = idx >> 15;            // ND = 32
    int w0 = w4 << 2;

    const float PI = 3.14159265358979323846f;
    float theta = ((float)h + 0.5f) * (PI / (float)HH) - 0.5f * PI;
    float st, ct;
    sincosf(theta, &st, &ct);

    int dhw = (d * HH + h) * WW + w0;
    float4 dep4 = *(const float4*)(depth + dhw);
    float depv[4] = {dep4.x, dep4.y, dep4.z, dep4.w};

    int   off[4][4];
    float wgt[4][4];

    #pragma unroll
    for (int j = 0; j < 4; j++) {
        float dvr = atanf((depv[j] * st + BASELINE_V) / (depv[j] * ct)) - theta;
        float dv  = dvr * ((float)HH / PI);
        float ypx = isfinite(dv) ? ((float)h + dv) : 0.0f;
        // grid normalize by (H-1)/2, then grid_sample unnormalize (align_corners=False):
        float iy = ypx * ((float)HH / ((float)HH - 1.0f)) - 0.5f;
        float ix = (float)(w0 + j) * ((float)WW / ((float)WW - 1.0f)) - 0.5f;

        float fx0 = floorf(ix), fy0 = floorf(iy);
        float wx = ix - fx0,    wy = iy - fy0;
        int x0 = (int)fx0, y0i = (int)fy0;
        int x1 = x0 + 1,   y1i = y0i + 1;

        float vx0 = (x0 >= 0 && x0 < WW) ? 1.0f : 0.0f;
        float vx1 = (x1 >= 0 && x1 < WW) ? 1.0f : 0.0f;
        float vy0 = (y0i >= 0 && y0i < HH) ? 1.0f : 0.0f;
        float vy1 = (y1i >= 0 && y1i < HH) ? 1.0f : 0.0f;

        int xc0 = min(max(x0, 0), WW - 1);
        int xc1 = min(max(x1, 0), WW - 1);
        int yc0 = min(max(y0i, 0), HH - 1);
        int yc1 = min(max(y1i, 0), HH - 1);

        off[j][0] = yc0 * WW + xc0;  wgt[j][0] = (1.0f - wx) * (1.0f - wy) * vx0 * vy0;
        off[j][1] = yc0 * WW + xc1;  wgt[j][1] = wx          * (1.0f - wy) * vx1 * vy0;
        off[j][2] = yc1 * WW + xc0;  wgt[j][2] = (1.0f - wx) * wy          * vx0 * vy1;
        off[j][3] = yc1 * WW + xc1;  wgt[j][3] = wx          * wy          * vx1 * vy1;
    }

    int out_base = (d * HH + h) * WW + w0;
    const float* xp = x + h * WW + w0;

    #pragma unroll 4
    for (int c = 0; c < CC; c++) {
        // reference channel: broadcast x over disparity
        float4 xv = *(const float4*)(xp + c * HW);
        __stcs((float4*)(out + (size_t)c * (ND * HW) + out_base), xv);

        // warped channel: bilinear gather of y
        const float* yc = y + c * HW;
        float acc0 = 0.0f, acc1 = 0.0f, acc2 = 0.0f, acc3 = 0.0f;
        #pragma unroll
        for (int k = 0; k < 4; k++) {
            acc0 += __ldg(yc + off[0][k]) * wgt[0][k];
            acc1 += __ldg(yc + off[1][k]) * wgt[1][k];
            acc2 += __ldg(yc + off[2][k]) * wgt[2][k];
            acc3 += __ldg(yc + off[3][k]) * wgt[3][k];
        }
        float4 r = make_float4(acc0, acc1, acc2, acc3);
        __stcs((float4*)(out + (size_t)(CC + c) * (ND * HW) + out_base), r);
    }
}

extern "C" void kernel_launch(void* const* d_in, const int* in_sizes, int n_in,
                              void* d_out, int out_size) {
    const float* x     = (const float*)d_in[0];
    const float* y     = (const float*)d_in[1];
    const float* depth = (const float*)d_in[2];
    float* out = (float*)d_out;

    int total_threads = ND * HH * (WW / 4);   // 1,048,576
    int blocks = total_threads / 256;         // 4096
    cost_volume_kernel<<<blocks, 256>>>(x, y, depth, out);
}

// round 2
// speedup vs baseline: 1.1866x; 1.1866x over previous
#include <cuda_runtime.h>
#include <math.h>

#define HH 256
#define WW 512
#define CC 16
#define ND 32
#define HW (HH * WW)
#define BASELINE_V 0.24f

// y transposed to pixel-major: yT[pixel][16 channels], 64B per pixel
__device__ float g_yT[HW * CC];

// ---------------- Kernel 1: transpose y [C,H,W] -> yT[H*W][C] ----------------
__global__ __launch_bounds__(256) void transpose_y_kernel(const float* __restrict__ y)
{
    int p = blockIdx.x * 256 + threadIdx.x;   // HW threads
    float v[CC];
    #pragma unroll
    for (int c = 0; c < CC; c++) v[c] = __ldg(y + c * HW + p);
    float4* o = (float4*)(g_yT + (size_t)p * CC);
    o[0] = make_float4(v[0],  v[1],  v[2],  v[3]);
    o[1] = make_float4(v[4],  v[5],  v[6],  v[7]);
    o[2] = make_float4(v[8],  v[9],  v[10], v[11]);
    o[3] = make_float4(v[12], v[13], v[14], v[15]);
}

// ---------------- Kernel 2: broadcast x into channels [0,16) ----------------
// out[c][d][h][w] = x[c][h][w]; read x once, 32 streaming stores.
__global__ __launch_bounds__(256) void bcast_x_kernel(const float* __restrict__ x,
                                                      float* __restrict__ out)
{
    int i = blockIdx.x * 256 + threadIdx.x;   // CC*HW/4 threads = 524288
    int c   = i / (HW / 4);
    int hw4 = i - c * (HW / 4);
    float4 v = ((const float4*)x)[i];
    float4* ob = (float4*)(out + (size_t)c * (ND * HW)) + hw4;
    #pragma unroll
    for (int d = 0; d < ND; d++)
        __stcs(ob + d * (HW / 4), v);
}

// ---------------- Kernel 3: bilinear gather into channels [16,32) ----------------
__global__ __launch_bounds__(256) void gather_y_kernel(const float* __restrict__ depth,
                                                       float* __restrict__ out)
{
    int idx = blockIdx.x * 256 + threadIdx.x;   // ND*HW threads
    int w = idx & (WW - 1);
    int h = (idx >> 9) & (HH - 1);

    const float PI = 3.14159265358979323846f;
    float theta = ((float)h + 0.5f) * (PI / (float)HH) - 0.5f * PI;
    float st, ct;
    sincosf(theta, &st, &ct);

    float dep = __ldg(depth + idx);
    float dvr = atanf((dep * st + BASELINE_V) / (dep * ct)) - theta;
    float dv  = dvr * ((float)HH / PI);
    float ypx = isfinite(dv) ? ((float)h + dv) : 0.0f;

    // grid normalize by (H-1)/2 then unnormalize align_corners=False
    float iy = ypx * ((float)HH / ((float)HH - 1.0f)) - 0.5f;
    float ix = (float)w * ((float)WW / ((float)WW - 1.0f)) - 0.5f;

    float fx0 = floorf(ix), fy0 = floorf(iy);
    float wx = ix - fx0,    wy = iy - fy0;
    int x0 = (int)fx0, y0i = (int)fy0;
    int x1 = x0 + 1,   y1i = y0i + 1;

    float vx0 = (x0 >= 0 && x0 < WW) ? 1.0f : 0.0f;
    float vx1 = (x1 >= 0 && x1 < WW) ? 1.0f : 0.0f;
    float vy0 = (y0i >= 0 && y0i < HH) ? 1.0f : 0.0f;
    float vy1 = (y1i >= 0 && y1i < HH) ? 1.0f : 0.0f;

    int xc0 = min(max(x0, 0), WW - 1);
    int xc1 = min(max(x1, 0), WW - 1);
    int yc0 = min(max(y0i, 0), HH - 1);
    int yc1 = min(max(y1i, 0), HH - 1);

    // pixel indices of the 4 corners (each 64B-aligned chunk of 16 ch in yT)
    int p00 = yc0 * WW + xc0;
    int p01 = yc0 * WW + xc1;
    int p10 = yc1 * WW + xc0;
    int p11 = yc1 * WW + xc1;

    float w00 = (1.0f - wx) * (1.0f - wy) * vx0 * vy0;
    float w01 = wx          * (1.0f - wy) * vx1 * vy0;
    float w10 = (1.0f - wx) * wy          * vx0 * vy1;
    float w11 = wx          * wy          * vx1 * vy1;

    const float4* yT4 = (const float4*)g_yT;
    float4 acc[4];
    #pragma unroll
    for (int ch = 0; ch < 4; ch++) {
        float4 a = __ldg(yT4 + (size_t)p00 * 4 + ch);
        float4 b = __ldg(yT4 + (size_t)p01 * 4 + ch);
        float4 c = __ldg(yT4 + (size_t)p10 * 4 + ch);
        float4 e = __ldg(yT4 + (size_t)p11 * 4 + ch);
        acc[ch].x = fmaf(w00, a.x, fmaf(w01, b.x, fmaf(w10, c.x, w11 * e.x)));
        acc[ch].y = fmaf(w00, a.y, fmaf(w01, b.y, fmaf(w10, c.y, w11 * e.y)));
        acc[ch].z = fmaf(w00, a.z, fmaf(w01, b.z, fmaf(w10, c.z, w11 * e.z)));
        acc[ch].w = fmaf(w00, a.w, fmaf(w01, b.w, fmaf(w10, c.w, w11 * e.w)));
    }

    float* ob = out + (size_t)CC * (ND * HW) + idx;
    #pragma unroll
    for (int ch = 0; ch < 4; ch++) {
        __stcs(ob + (size_t)(ch * 4 + 0) * (ND * HW), acc[ch].x);
        __stcs(ob + (size_t)(ch * 4 + 1) * (ND * HW), acc[ch].y);
        __stcs(ob + (size_t)(ch * 4 + 2) * (ND * HW), acc[ch].z);
        __stcs(ob + (size_t)(ch * 4 + 3) * (ND * HW), acc[ch].w);
    }
}

extern "C" void kernel_launch(void* const* d_in, const int* in_sizes, int n_in,
                              void* d_out, int out_size) {
    const float* x     = (const float*)d_in[0];
    const float* y     = (const float*)d_in[1];
    const float* depth = (const float*)d_in[2];
    float* out = (float*)d_out;

    transpose_y_kernel<<<HW / 256, 256>>>(y);
    gather_y_kernel<<<(ND * HW) / 256, 256>>>(depth, out);
    bcast_x_kernel<<<(CC * HW / 4) / 256, 256>>>(x, out);
}

// round 3
// speedup vs baseline: 2.0593x; 1.7354x over previous
#include <cuda_runtime.h>
#include <math.h>

#define HH 256
#define WW 512
#define CC 16
#define ND 32
#define HW (HH * WW)
#define NDHW (ND * HW)
#define BASELINE_V 0.24f

// y transposed into 4 channel-chunk planes: g_yTc[chunk*HW + pixel] = {ch0..ch3} of that chunk
__device__ float4 g_yTc[4 * HW];

// ---------------- Kernel 1: transpose y [C,H,W] -> 4 planes of [H*W][4ch] ----------------
__global__ __launch_bounds__(256) void transpose_y_kernel(const float* __restrict__ y)
{
    int p = blockIdx.x * 256 + threadIdx.x;   // HW threads
    float v[CC];
    #pragma unroll
    for (int c = 0; c < CC; c++) v[c] = __ldg(y + c * HW + p);
    g_yTc[0 * HW + p] = make_float4(v[0],  v[1],  v[2],  v[3]);
    g_yTc[1 * HW + p] = make_float4(v[4],  v[5],  v[6],  v[7]);
    g_yTc[2 * HW + p] = make_float4(v[8],  v[9],  v[10], v[11]);
    g_yTc[3 * HW + p] = make_float4(v[12], v[13], v[14], v[15]);
}

// ---------------- Kernel 2: fused broadcast + bilinear gather ----------------
// grid (2, HH, 4): (w-tile, h, chunk).  Thread: one (w, h, chunk), loops all 32 d.
__global__ __launch_bounds__(256) void fused_cv_kernel(const float* __restrict__ x,
                                                       const float* __restrict__ depth,
                                                       float* __restrict__ out)
{
    int w     = blockIdx.x * 256 + threadIdx.x;
    int h     = blockIdx.y;
    int chunk = blockIdx.z;
    int c0    = chunk * 4;

    // x values for this pixel's 4 channels (d-invariant)
    int hw = h * WW + w;
    float x0v = __ldg(x + (c0 + 0) * HW + hw);
    float x1v = __ldg(x + (c0 + 1) * HW + hw);
    float x2v = __ldg(x + (c0 + 2) * HW + hw);
    float x3v = __ldg(x + (c0 + 3) * HW + hw);

    const float PI = 3.14159265358979323846f;
    float theta = ((float)h + 0.5f) * (PI / (float)HH) - 0.5f * PI;
    float st, ct;
    sincosf(theta, &st, &ct);

    // horizontal corner data (d-invariant)
    float ix = (float)w * ((float)WW / ((float)WW - 1.0f)) - 0.5f;
    float fx0 = floorf(ix);
    float wx  = ix - fx0;
    int xi0 = (int)fx0, xi1 = xi0 + 1;
    float vx0 = (xi0 >= 0 && xi0 < WW) ? 1.0f : 0.0f;
    float vx1 = (xi1 >= 0 && xi1 < WW) ? 1.0f : 0.0f;
    int xc0 = min(max(xi0, 0), WW - 1);
    int xc1 = min(max(xi1, 0), WW - 1);

    const float4* __restrict__ plane = g_yTc + (size_t)chunk * HW;
    const float* dp = depth + hw;

    float* ob_x = out + (size_t)c0 * NDHW + hw;          // broadcast half, ch c0
    float* ob_y = out + (size_t)(CC + c0) * NDHW + hw;   // warped half, ch 16+c0

    #pragma unroll 2
    for (int d = 0; d < ND; d++) {
        float dep = __ldg(dp + d * HW);
        float dvr = atanf((dep * st + BASELINE_V) / (dep * ct)) - theta;
        float dv  = dvr * ((float)HH / PI);
        float ypx = isfinite(dv) ? ((float)h + dv) : 0.0f;
        float iy  = ypx * ((float)HH / ((float)HH - 1.0f)) - 0.5f;

        float fy0 = floorf(iy);
        float wy  = iy - fy0;
        int yi0 = (int)fy0, yi1 = yi0 + 1;
        float vy0 = (yi0 >= 0 && yi0 < HH) ? 1.0f : 0.0f;
        float vy1 = (yi1 >= 0 && yi1 < HH) ? 1.0f : 0.0f;
        int yc0 = min(max(yi0, 0), HH - 1);
        int yc1 = min(max(yi1, 0), HH - 1);

        float w00 = (1.0f - wx) * (1.0f - wy) * vx0 * vy0;
        float w01 = wx          * (1.0f - wy) * vx1 * vy0;
        float w10 = (1.0f - wx) * wy          * vx0 * vy1;
        float w11 = wx          * wy          * vx1 * vy1;

        float4 a = __ldg(plane + yc0 * WW + xc0);
        float4 b = __ldg(plane + yc0 * WW + xc1);
        float4 c = __ldg(plane + yc1 * WW + xc0);
        float4 e = __ldg(plane + yc1 * WW + xc1);

        float r0 = fmaf(w00, a.x, fmaf(w01, b.x, fmaf(w10, c.x, w11 * e.x)));
        float r1 = fmaf(w00, a.y, fmaf(w01, b.y, fmaf(w10, c.y, w11 * e.y)));
        float r2 = fmaf(w00, a.z, fmaf(w01, b.z, fmaf(w10, c.z, w11 * e.z)));
        float r3 = fmaf(w00, a.w, fmaf(w01, b.w, fmaf(w10, c.w, w11 * e.w)));

        int od = d * HW;
        __stcs(ob_y + od + 0 * NDHW, r0);
        __stcs(ob_y + od + 1 * NDHW, r1);
        __stcs(ob_y + od + 2 * NDHW, r2);
        __stcs(ob_y + od + 3 * NDHW, r3);

        __stcs(ob_x + od + 0 * NDHW, x0v);
        __stcs(ob_x + od + 1 * NDHW, x1v);
        __stcs(ob_x + od + 2 * NDHW, x2v);
        __stcs(ob_x + od + 3 * NDHW, x3v);
    }
}

extern "C" void kernel_launch(void* const* d_in, const int* in_sizes, int n_in,
                              void* d_out, int out_size) {
    const float* x     = (const float*)d_in[0];
    const float* y     = (const float*)d_in[1];
    const float* depth = (const float*)d_in[2];
    float* out = (float*)d_out;

    transpose_y_kernel<<<HW / 256, 256>>>(y);
    dim3 grid(WW / 256, HH, 4);
    fused_cv_kernel<<<grid, 256>>>(x, depth, out);
}

// round 4
// speedup vs baseline: 2.3986x; 1.1648x over previous
#include <cuda_runtime.h>
#include <math.h>

#define HH 256
#define WW 512
#define CC 16
#define ND 32
#define HW (HH * WW)
#define NDHW (ND * HW)
#define BASELINE_V 0.24f

// Horizontally pre-interpolated y, in 4 channel-chunk planes:
// g_Z[chunk*HW + r*WW + w] = {4 channels} of (1-wx)*vx0*y[r][xc0] + wx*vx1*y[r][xc1]
__device__ float4 g_Z[4 * HW];

// ---------------- Kernel 1: horizontal interp + transpose ----------------
__global__ __launch_bounds__(256) void hinterp_kernel(const float* __restrict__ y)
{
    int p = blockIdx.x * 256 + threadIdx.x;   // HW threads
    int w = p & (WW - 1);
    int rbase = p - w;                        // r * WW

    // d-invariant horizontal sample position (align_corners=False unnormalize
    // of grid normalized by (W-1)/2)
    float ix = (float)w * ((float)WW / ((float)WW - 1.0f)) - 0.5f;
    float fx0 = floorf(ix);
    float wx  = ix - fx0;
    int xi0 = (int)fx0, xi1 = xi0 + 1;
    float w0x = (xi0 >= 0 && xi0 < WW) ? (1.0f - wx) : 0.0f;
    float w1x = (xi1 >= 0 && xi1 < WW) ? wx : 0.0f;
    int xc0 = min(max(xi0, 0), WW - 1);
    int xc1 = min(max(xi1, 0), WW - 1);

    #pragma unroll
    for (int chunk = 0; chunk < 4; chunk++) {
        float v[4];
        #pragma unroll
        for (int c = 0; c < 4; c++) {
            const float* yc = y + (chunk * 4 + c) * HW + rbase;
            v[c] = w0x * __ldg(yc + xc0) + w1x * __ldg(yc + xc1);
        }
        g_Z[chunk * HW + p] = make_float4(v[0], v[1], v[2], v[3]);
    }
}

// ---------------- Kernel 2: fused broadcast + vertical interp ----------------
// grid (2, HH, 4): (w-tile, h, chunk). Thread: one (w, h, chunk), loops all 32 d.
__global__ __launch_bounds__(256) void fused_cv_kernel(const float* __restrict__ x,
                                                       const float* __restrict__ depth,
                                                       float* __restrict__ out)
{
    int w     = blockIdx.x * 256 + threadIdx.x;
    int h     = blockIdx.y;
    int chunk = blockIdx.z;
    int c0    = chunk * 4;

    int hw = h * WW + w;
    float x0v = __ldg(x + (c0 + 0) * HW + hw);
    float x1v = __ldg(x + (c0 + 1) * HW + hw);
    float x2v = __ldg(x + (c0 + 2) * HW + hw);
    float x3v = __ldg(x + (c0 + 3) * HW + hw);

    const float PI = 3.14159265358979323846f;
    float theta = ((float)h + 0.5f) * (PI / (float)HH) - 0.5f * PI;
    float st, ct;
    sincosf(theta, &st, &ct);

    const float4* __restrict__ plane = g_Z + (size_t)chunk * HW;
    const float* dp = depth + hw;

    float* ob_x = out + (size_t)c0 * NDHW + hw;          // broadcast half
    float* ob_y = out + (size_t)(CC + c0) * NDHW + hw;   // warped half

    #pragma unroll 2
    for (int d = 0; d < ND; d++) {
        float dep = __ldg(dp + d * HW);
        float dvr = atanf((dep * st + BASELINE_V) / (dep * ct)) - theta;
        float dv  = dvr * ((float)HH / PI);
        float ypx = isfinite(dv) ? ((float)h + dv) : 0.0f;
        float iy  = ypx * ((float)HH / ((float)HH - 1.0f)) - 0.5f;

        float fy0 = floorf(iy);
        float wy  = iy - fy0;
        int yi0 = (int)fy0, yi1 = yi0 + 1;
        float wA = (yi0 >= 0 && yi0 < HH) ? (1.0f - wy) : 0.0f;
        float wB = (yi1 >= 0 && yi1 < HH) ? wy : 0.0f;
        int yc0 = min(max(yi0, 0), HH - 1);
        int yc1 = min(max(yi1, 0), HH - 1);

        float4 a = __ldg(plane + yc0 * WW + w);
        float4 b = __ldg(plane + yc1 * WW + w);

        float r0 = fmaf(wA, a.x, wB * b.x);
        float r1 = fmaf(wA, a.y, wB * b.y);
        float r2 = fmaf(wA, a.z, wB * b.z);
        float r3 = fmaf(wA, a.w, wB * b.w);

        int od = d * HW;
        __stcs(ob_y + od + 0 * NDHW, r0);
        __stcs(ob_y + od + 1 * NDHW, r1);
        __stcs(ob_y + od + 2 * NDHW, r2);
        __stcs(ob_y + od + 3 * NDHW, r3);

        __stcs(ob_x + od + 0 * NDHW, x0v);
        __stcs(ob_x + od + 1 * NDHW, x1v);
        __stcs(ob_x + od + 2 * NDHW, x2v);
        __stcs(ob_x + od + 3 * NDHW, x3v);
    }
}

extern "C" void kernel_launch(void* const* d_in, const int* in_sizes, int n_in,
                              void* d_out, int out_size) {
    const float* x     = (const float*)d_in[0];
    const float* y     = (const float*)d_in[1];
    const float* depth = (const float*)d_in[2];
    float* out = (float*)d_out;

    hinterp_kernel<<<HW / 256, 256>>>(y);
    dim3 grid(WW / 256, HH, 4);
    fused_cv_kernel<<<grid, 256>>>(x, depth, out);
}